// round 11
// baseline (speedup 1.0000x reference)
#include <cuda_runtime.h>
#include <cuda_bf16.h>
#include <cstdint>

#define B_ 64
#define S_ 512
#define E_ 256
#define H_ 1024
#define V_ 128

#define NCTA 64          // persistent CTAs (1/SM, all resident in wave 1)
#define TPB 256          // 8 warps
#define COLS 16          // hidden columns owned per CTA
#define PAIRS 512        // H/2 bf16x2 pairs per row
#define USTW 516         // padded smem row stride in words (516%32==4 -> conflict-free)
#define SLOTW (B_ * PAIRS)   // 32768 words per h-slot

// ---------------- persistent device scratch (static: no allocations) ----------------
__device__ uint32_t g_hh_hi[(S_ + 1) * SLOTW];  // h_0..h_512 hi(bf16) pairs
__device__ uint32_t g_hh_lo[(S_ + 1) * SLOTW];  // lo residual pairs
__device__ uint32_t g_rh_hi[SLOTW];             // r*h broadcast (per step)
__device__ uint32_t g_rh_lo[SLOTW];
__device__ uint32_t g_wfc_hi[V_ * PAIRS];       // W_fc split
__device__ uint32_t g_wfc_lo[V_ * PAIRS];
__device__ float    g_eproj[3][V_ * H_];        // embproj tables (r,z,h gates)
__device__ unsigned g_cnt;                      // global barrier counter

// ---------------- helpers ----------------
// split two consecutive fp32 (even k in low half) into packed bf16x2 hi + lo words
__device__ __forceinline__ void split2(float a, float b, uint32_t& whi, uint32_t& wlo) {
    __nv_bfloat16 ah = __float2bfloat16_rn(a);
    __nv_bfloat16 bh = __float2bfloat16_rn(b);
    float ar = a - __bfloat162float(ah);
    float br = b - __bfloat162float(bh);
    __nv_bfloat162 vh; vh.x = ah; vh.y = bh;
    __nv_bfloat162 vl; vl.x = __float2bfloat16_rn(ar); vl.y = __float2bfloat16_rn(br);
    whi = *reinterpret_cast<uint32_t*>(&vh);
    wlo = *reinterpret_cast<uint32_t*>(&vl);
}

__device__ __forceinline__ void mma16(float* c, uint32_t a0, uint32_t a1, uint32_t a2,
                                      uint32_t a3, uint32_t b0, uint32_t b1) {
    asm volatile(
        "mma.sync.aligned.m16n8k16.row.col.f32.bf16.bf16.f32 "
        "{%0,%1,%2,%3},{%4,%5,%6,%7},{%8,%9},{%0,%1,%2,%3};"
        : "+f"(c[0]), "+f"(c[1]), "+f"(c[2]), "+f"(c[3])
        : "r"(a0), "r"(a1), "r"(a2), "r"(a3), "r"(b0), "r"(b1));
}

// 3-term split-bf16 mma: acc += Ahi*Bhi + Alo*Bhi + Ahi*Blo
__device__ __forceinline__ void mma3(float* c, const uint32_t* ah, const uint32_t* al,
                                     uint32_t bh0, uint32_t bh1, uint32_t bl0, uint32_t bl1) {
    mma16(c, ah[0], ah[1], ah[2], ah[3], bh0, bh1);
    mma16(c, al[0], al[1], al[2], al[3], bh0, bh1);
    mma16(c, ah[0], ah[1], ah[2], ah[3], bl0, bl1);
}

// grid-wide barrier: all NCTA CTAs resident by construction.
__device__ __forceinline__ void gbar(unsigned target) {
    __syncthreads();
    if (threadIdx.x == 0) {
        __threadfence();
        atomicAdd(&g_cnt, 1u);
        while (atomicAdd(&g_cnt, 0u) < target) {}
    }
    __syncthreads();
    __threadfence();
}

// ---------------- init: zero h_0 split slot, reset barrier counter ----------------
__global__ void k_init() {
    int i = blockIdx.x * blockDim.x + threadIdx.x;   // 16384 threads
    uint2 z = make_uint2(0u, 0u);
    ((uint2*)g_hh_hi)[i] = z;                        // 32768 words = slot 0
    ((uint2*)g_hh_lo)[i] = z;
    if (i == 0) g_cnt = 0u;
}

// ---------------- W_fc split precompute ----------------
__global__ void k_wfcsplit(const float* __restrict__ Wfc) {
    int i = blockIdx.x * blockDim.x + threadIdx.x;   // 65536 pairs
    float2 v = ((const float2*)Wfc)[i];
    uint32_t hi, lo;
    split2(v.x, v.y, hi, lo);
    g_wfc_hi[i] = hi;
    g_wfc_lo[i] = lo;
}

// ---------------- embproj: eproj[g][v][h] = emb[v,:] @ W_g[h,:]^T + 2*b_g[h] ----------------
__global__ void __launch_bounds__(256) k_embproj(const float* __restrict__ emb,
                                                 const float* __restrict__ Wr,
                                                 const float* __restrict__ Wz,
                                                 const float* __restrict__ Wh,
                                                 const float* __restrict__ br,
                                                 const float* __restrict__ bz,
                                                 const float* __restrict__ bh) {
    int wt   = (blockIdx.x * blockDim.x + threadIdx.x) >> 5;  // 0..3071
    int lane = threadIdx.x & 31;
    int g    = wt >> 10;
    int rem  = wt & 1023;
    int mi   = rem >> 7;    // 0..7   (16-row vocab tile)
    int ni   = rem & 127;   // 0..127 (8-col hidden tile)

    const float* W    = (g == 0) ? Wr : ((g == 1) ? Wz : Wh);
    const float* bias = (g == 0) ? br : ((g == 1) ? bz : bh);

    int r0 = 16 * mi + (lane >> 2), r1 = r0 + 8;
    int pb = lane & 3;
    const float* pA0 = emb + r0 * E_ + 2 * pb;
    const float* pA1 = emb + r1 * E_ + 2 * pb;
    const float* pB  = W + (8 * ni + (lane >> 2)) * E_ + 2 * pb;

    float acc[4] = {0.f, 0.f, 0.f, 0.f};
#pragma unroll
    for (int kp = 0; kp < E_ / 2; kp += 8) {    // 16 iters of k16
        float2 va0 = *(const float2*)(pA0 + 2 * kp);
        float2 va2 = *(const float2*)(pA0 + 2 * kp + 8);
        float2 va1 = *(const float2*)(pA1 + 2 * kp);
        float2 va3 = *(const float2*)(pA1 + 2 * kp + 8);
        uint32_t ah[4], al[4];
        split2(va0.x, va0.y, ah[0], al[0]);
        split2(va1.x, va1.y, ah[1], al[1]);
        split2(va2.x, va2.y, ah[2], al[2]);
        split2(va3.x, va3.y, ah[3], al[3]);
        float2 vb0 = *(const float2*)(pB + 2 * kp);
        float2 vb1 = *(const float2*)(pB + 2 * kp + 8);
        uint32_t bh0, bl0, bh1, bl1;
        split2(vb0.x, vb0.y, bh0, bl0);
        split2(vb1.x, vb1.y, bh1, bl1);
        mma3(acc, ah, al, bh0, bh1, bl0, bl1);
    }
#pragma unroll
    for (int i = 0; i < 4; i++) {
        int row = (i >= 2) ? r1 : r0;
        int col = 8 * ni + 2 * pb + (i & 1);
        g_eproj[g][row * H_ + col] = acc[i] + 2.0f * bias[col];
    }
}

// ---------------- persistent GRU recurrence (split-bf16 3-mma) ----------------
__global__ void __launch_bounds__(TPB, 1) k_gru(const int* __restrict__ x,
                                                const float* __restrict__ Ur,
                                                const float* __restrict__ Uz,
                                                const float* __restrict__ Uh) {
    extern __shared__ uint32_t smw[];
    const int GATE = COLS * USTW;     // 8256 words per array
    uint32_t* sUrHi = smw;
    uint32_t* sUrLo = smw + GATE;
    uint32_t* sUzHi = smw + 2 * GATE;
    uint32_t* sUzLo = smw + 3 * GATE;
    uint32_t* sUhHi = smw + 4 * GATE;
    uint32_t* sUhLo = smw + 5 * GATE;

    int tid = threadIdx.x;
    int cta = blockIdx.x;
    int c0  = cta * COLS;

    // load + split this CTA's U column-slices into SMEM
    for (int g = 0; g < 3; g++) {
        const float* U = (g == 0) ? Ur : ((g == 1) ? Uz : Uh);
        uint32_t* dHi = smw + (2 * g) * GATE;
        uint32_t* dLo = dHi + GATE;
        for (int i = tid; i < COLS * PAIRS; i += TPB) {
            int c = i >> 9, kp = i & 511;
            float2 v = *(const float2*)(U + (size_t)(c0 + c) * H_ + 2 * kp);
            uint32_t hi, lo;
            split2(v.x, v.y, hi, lo);
            dHi[c * USTW + kp] = hi;
            dLo[c * USTW + kp] = lo;
        }
    }
    __syncthreads();

    int w = tid >> 5, lane = tid & 31;
    int mi = w >> 1, ni = w & 1;                 // 4 m-tiles x 2 n-tiles
    int r0 = 16 * mi + (lane >> 2), r1 = r0 + 8;
    int pb = lane & 3;

    int urow = (8 * ni + (lane >> 2)) * USTW + pb;
    const uint32_t* pUrHi = sUrHi + urow;
    const uint32_t* pUrLo = sUrLo + urow;
    const uint32_t* pUzHi = sUzHi + urow;
    const uint32_t* pUzLo = sUzLo + urow;
    const uint32_t* pUhHi = sUhHi + urow;
    const uint32_t* pUhLo = sUhLo + urow;

    int offA0 = r0 * PAIRS + pb;
    int offA1 = r1 * PAIRS + pb;
    int colBase = c0 + 8 * ni + 2 * pb;          // even
    int pidx = (colBase >> 1);                   // pair index within row

    int tok0 = 0, tok1 = 0;
    float h_own[4] = {0.f, 0.f, 0.f, 0.f};       // this thread's h values
    unsigned target = 0;

    for (int t = 0; t < S_; ++t) {
        const uint32_t* hhHi = g_hh_hi + t * SLOTW;
        const uint32_t* hhLo = g_hh_lo + t * SLOTW;

        // ---- phase 1: r,z gates ----
        float accR[4] = {0.f, 0.f, 0.f, 0.f};
        float accZ[4] = {0.f, 0.f, 0.f, 0.f};
#pragma unroll 4
        for (int kp = 0; kp < PAIRS; kp += 8) {
            uint32_t ah[4], al[4];
            ah[0] = hhHi[offA0 + kp];     ah[1] = hhHi[offA1 + kp];
            ah[2] = hhHi[offA0 + kp + 4]; ah[3] = hhHi[offA1 + kp + 4];
            al[0] = hhLo[offA0 + kp];     al[1] = hhLo[offA1 + kp];
            al[2] = hhLo[offA0 + kp + 4]; al[3] = hhLo[offA1 + kp + 4];
            mma3(accR, ah, al, pUrHi[kp], pUrHi[kp + 4], pUrLo[kp], pUrLo[kp + 4]);
            mma3(accZ, ah, al, pUzHi[kp], pUzHi[kp + 4], pUzLo[kp], pUzLo[kp + 4]);
        }

        tok0 = x[r0 * S_ + t];
        tok1 = x[r1 * S_ + t];
        float zv[4], rh[4];
#pragma unroll
        for (int i = 0; i < 4; i++) {
            int tok = (i >= 2) ? tok1 : tok0;
            int col = colBase + (i & 1);
            float xr = g_eproj[0][tok * H_ + col];
            float xz = g_eproj[1][tok * H_ + col];
            float rg = 1.f / (1.f + __expf(-(accR[i] + xr)));
            zv[i]    = 1.f / (1.f + __expf(-(accZ[i] + xz)));
            rh[i]    = rg * h_own[i];
        }
        {
            uint32_t hi, lo;
            split2(rh[0], rh[1], hi, lo);
            g_rh_hi[r0 * PAIRS + pidx] = hi;
            g_rh_lo[r0 * PAIRS + pidx] = lo;
            split2(rh[2], rh[3], hi, lo);
            g_rh_hi[r1 * PAIRS + pidx] = hi;
            g_rh_lo[r1 * PAIRS + pidx] = lo;
        }
        target += NCTA;
        gbar(target);

        // ---- phase 2: candidate h, state update ----
        float accH[4] = {0.f, 0.f, 0.f, 0.f};
#pragma unroll 4
        for (int kp = 0; kp < PAIRS; kp += 8) {
            uint32_t ah[4], al[4];
            ah[0] = g_rh_hi[offA0 + kp];     ah[1] = g_rh_hi[offA1 + kp];
            ah[2] = g_rh_hi[offA0 + kp + 4]; ah[3] = g_rh_hi[offA1 + kp + 4];
            al[0] = g_rh_lo[offA0 + kp];     al[1] = g_rh_lo[offA1 + kp];
            al[2] = g_rh_lo[offA0 + kp + 4]; al[3] = g_rh_lo[offA1 + kp + 4];
            mma3(accH, ah, al, pUhHi[kp], pUhHi[kp + 4], pUhLo[kp], pUhLo[kp + 4]);
        }
        uint32_t* nhHi = g_hh_hi + (t + 1) * SLOTW;
        uint32_t* nhLo = g_hh_lo + (t + 1) * SLOTW;
#pragma unroll
        for (int i = 0; i < 4; i++) {
            int tok = (i >= 2) ? tok1 : tok0;
            int col = colBase + (i & 1);
            float xh = g_eproj[2][tok * H_ + col];
            float ht = tanhf(accH[i] + xh);
            h_own[i] = (1.f - zv[i]) * ht + zv[i] * h_own[i];
        }
        {
            uint32_t hi, lo;
            split2(h_own[0], h_own[1], hi, lo);
            nhHi[r0 * PAIRS + pidx] = hi;
            nhLo[r0 * PAIRS + pidx] = lo;
            split2(h_own[2], h_own[3], hi, lo);
            nhHi[r1 * PAIRS + pidx] = hi;
            nhLo[r1 * PAIRS + pidx] = lo;
        }
        target += NCTA;
        gbar(target);
    }
}

// ---------------- logits: [32768,1024] @ [1024,128]^T + b_fc (split-bf16) ----------------
__global__ void __launch_bounds__(256) k_logits(const float* __restrict__ bfc,
                                                float* __restrict__ out) {
    int w = threadIdx.x >> 5, lane = threadIdx.x & 31;
    int rowTile = blockIdx.x * 8 + w;                 // 0..2047
    int r0 = rowTile * 16 + (lane >> 2), r1 = r0 + 8;
    int pb = lane & 3;

    const uint32_t* pA0hi = g_hh_hi + SLOTW + (size_t)r0 * PAIRS + pb;  // skip slot 0
    const uint32_t* pA1hi = g_hh_hi + SLOTW + (size_t)r1 * PAIRS + pb;
    const uint32_t* pA0lo = g_hh_lo + SLOTW + (size_t)r0 * PAIRS + pb;
    const uint32_t* pA1lo = g_hh_lo + SLOTW + (size_t)r1 * PAIRS + pb;
    const uint32_t* pBh = g_wfc_hi + (lane >> 2) * PAIRS + pb;
    const uint32_t* pBl = g_wfc_lo + (lane >> 2) * PAIRS + pb;

    float acc[16][4];
#pragma unroll
    for (int nt = 0; nt < 16; nt++)
#pragma unroll
        for (int i = 0; i < 4; i++) acc[nt][i] = 0.f;

    for (int kp = 0; kp < PAIRS; kp += 8) {
        uint32_t ah[4], al[4];
        ah[0] = pA0hi[kp];     ah[1] = pA1hi[kp];
        ah[2] = pA0hi[kp + 4]; ah[3] = pA1hi[kp + 4];
        al[0] = pA0lo[kp];     al[1] = pA1lo[kp];
        al[2] = pA0lo[kp + 4]; al[3] = pA1lo[kp + 4];
#pragma unroll
        for (int nt = 0; nt < 16; nt++) {
            int o = nt * 8 * PAIRS + kp;
            mma3(acc[nt], ah, al, pBh[o], pBh[o + 4], pBl[o], pBl[o + 4]);
        }
    }
#pragma unroll
    for (int nt = 0; nt < 16; nt++)
#pragma unroll
        for (int i = 0; i < 4; i++) {
            int row = (i >= 2) ? r1 : r0;
            int v   = nt * 8 + 2 * pb + (i & 1);
            int s   = row >> 6;
            int b   = row & 63;
            out[b * (S_ * V_) + s * V_ + v] = acc[nt][i] + bfc[v];
        }
}

// ---------------- h_last: reconstruct fp32 from split slot 512 ----------------
__global__ void k_hlast(float* __restrict__ out) {
    int i = blockIdx.x * blockDim.x + threadIdx.x;    // 32768 pairs
    uint32_t whi = g_hh_hi[S_ * SLOTW + i];
    uint32_t wlo = g_hh_lo[S_ * SLOTW + i];
    __nv_bfloat162 vh = *reinterpret_cast<__nv_bfloat162*>(&whi);
    __nv_bfloat162 vl = *reinterpret_cast<__nv_bfloat162*>(&wlo);
    int b = i >> 9, p = i & 511;
    float* o = out + (size_t)B_ * S_ * V_ + b * H_ + 2 * p;
    o[0] = __bfloat162float(vh.x) + __bfloat162float(vl.x);
    o[1] = __bfloat162float(vh.y) + __bfloat162float(vl.y);
}

// ---------------- launch ----------------
extern "C" void kernel_launch(void* const* d_in, const int* in_sizes, int n_in,
                              void* d_out, int out_size) {
    const int*   x   = (const int*)d_in[0];
    const float* emb = (const float*)d_in[1];
    const float* Wr  = (const float*)d_in[2];
    const float* Ur  = (const float*)d_in[3];
    const float* br  = (const float*)d_in[4];
    const float* Wz  = (const float*)d_in[5];
    const float* Uz  = (const float*)d_in[6];
    const float* bz  = (const float*)d_in[7];
    const float* Wh  = (const float*)d_in[8];
    const float* Uh  = (const float*)d_in[9];
    const float* bh  = (const float*)d_in[10];
    const float* Wfc = (const float*)d_in[11];
    const float* bfc = (const float*)d_in[12];
    float* out = (float*)d_out;

    const int smem_bytes = 6 * COLS * USTW * 4;  // 198144 B
    cudaFuncSetAttribute(k_gru, cudaFuncAttributeMaxDynamicSharedMemorySize,
                         smem_bytes);

    k_init<<<64, 256>>>();
    k_wfcsplit<<<256, 256>>>(Wfc);
    k_embproj<<<384, 256>>>(emb, Wr, Wz, Wh, br, bz, bh);
    k_gru<<<NCTA, TPB, smem_bytes>>>(x, Ur, Uz, Uh);
    k_logits<<<256, 256>>>(bfc, out);
    if (out_size >= B_ * S_ * V_ + B_ * H_) {
        k_hlast<<<128, 256>>>(out);
    }
}

// round 12
// speedup vs baseline: 2.1510x; 2.1510x over previous
#include <cuda_runtime.h>
#include <cuda_bf16.h>
#include <cstdint>

#define B_ 64
#define S_ 512
#define E_ 256
#define H_ 1024
#define V_ 128

#define NCTA 64            // persistent CTAs (1/SM, all resident in wave 1)
#define TPB 256            // 8 warps
#define COLS 16            // hidden columns owned per CTA
#define PAIRS 512          // H/2 bf16x2 pairs per row
#define SLOT 65536         // words per h-slot: 64 rows x 1024 words
#define UST 1028           // smem words per U column (1024 + 4 pad -> conflict-free)

// Fragment-major word layout within a row (1024 words = 4KB):
//   word(row, it, pb, c) = row*1024 + it*16 + pb*4 + c
//   c: 0=hi(p), 1=lo(p), 2=hi(p+4), 3=lo(p+4)   with p = it*8 + pb
// One LDG.128 per row-block per k16 iteration => fully coalesced 64B segments.

// ---------------- persistent device scratch ----------------
__device__ uint32_t g_hh[(S_ + 1) * SLOT];   // h_0..h_512 (hi/lo interleaved)
__device__ uint32_t g_rh[SLOT];              // r*h broadcast (per step)
__device__ uint32_t g_wfc[V_ * 1024];        // W_fc split, fragment-major
__device__ float    g_eproj[3][V_ * H_];     // embproj tables (r,z,h gates)
__device__ unsigned g_cnt;                   // global barrier counter

// ---------------- helpers ----------------
__device__ __forceinline__ void split2(float a, float b, uint32_t& whi, uint32_t& wlo) {
    __nv_bfloat16 ah = __float2bfloat16_rn(a);
    __nv_bfloat16 bh = __float2bfloat16_rn(b);
    float ar = a - __bfloat162float(ah);
    float br = b - __bfloat162float(bh);
    __nv_bfloat162 vh; vh.x = ah; vh.y = bh;
    __nv_bfloat162 vl; vl.x = __float2bfloat16_rn(ar); vl.y = __float2bfloat16_rn(br);
    whi = *reinterpret_cast<uint32_t*>(&vh);
    wlo = *reinterpret_cast<uint32_t*>(&vl);
}

__device__ __forceinline__ void mma16(float* c, uint32_t a0, uint32_t a1, uint32_t a2,
                                      uint32_t a3, uint32_t b0, uint32_t b1) {
    asm volatile(
        "mma.sync.aligned.m16n8k16.row.col.f32.bf16.bf16.f32 "
        "{%0,%1,%2,%3},{%4,%5,%6,%7},{%8,%9},{%0,%1,%2,%3};"
        : "+f"(c[0]), "+f"(c[1]), "+f"(c[2]), "+f"(c[3])
        : "r"(a0), "r"(a1), "r"(a2), "r"(a3), "r"(b0), "r"(b1));
}

// 3-term split mma: q0/q1 = (hi,lo,hi4,lo4) for rows r0/r1; b = (bh,bl,bh4,bl4)
__device__ __forceinline__ void mma3q(float* c, uint4 q0, uint4 q1, uint4 b) {
    mma16(c, q0.x, q1.x, q0.z, q1.z, b.x, b.z);   // Ahi*Bhi
    mma16(c, q0.y, q1.y, q0.w, q1.w, b.x, b.z);   // Alo*Bhi
    mma16(c, q0.x, q1.x, q0.z, q1.z, b.y, b.w);   // Ahi*Blo
}

// grid-wide barrier: all NCTA CTAs resident by construction.
// __threadfence() (gpu scope) emits CCTL.IVALL -> L1 invalidated so the
// subsequent cached loads observe remote CTAs' writes.
__device__ __forceinline__ void gbar(unsigned target) {
    __syncthreads();
    if (threadIdx.x == 0) {
        __threadfence();
        atomicAdd(&g_cnt, 1u);
        while (atomicAdd(&g_cnt, 0u) < target) {}
    }
    __syncthreads();
    __threadfence();
}

// ---------------- init: zero h_0 slot, reset barrier counter ----------------
__global__ void k_init() {
    int i = blockIdx.x * blockDim.x + threadIdx.x;   // 16384 threads x uint4
    ((uint4*)g_hh)[i] = make_uint4(0u, 0u, 0u, 0u);  // 65536 words = slot 0
    if (i == 0) g_cnt = 0u;
}

// ---------------- W_fc split + repack to fragment-major ----------------
__global__ void k_wfcsplit(const float* __restrict__ Wfc) {
    int i = blockIdx.x * blockDim.x + threadIdx.x;   // 65536 pairs
    int v = i >> 9, p = i & 511;
    float2 val = ((const float2*)Wfc)[i];
    uint32_t hi, lo;
    split2(val.x, val.y, hi, lo);
    int w = v * 1024 + (p >> 3) * 16 + (p & 3) * 4 + 2 * ((p >> 2) & 1);
    g_wfc[w]     = hi;
    g_wfc[w + 1] = lo;
}

// ---------------- embproj: eproj[g][v][h] = emb[v,:] @ W_g[h,:]^T + 2*b_g[h] ----------------
__global__ void __launch_bounds__(256) k_embproj(const float* __restrict__ emb,
                                                 const float* __restrict__ Wr,
                                                 const float* __restrict__ Wz,
                                                 const float* __restrict__ Wh,
                                                 const float* __restrict__ br,
                                                 const float* __restrict__ bz,
                                                 const float* __restrict__ bh) {
    int wt   = (blockIdx.x * blockDim.x + threadIdx.x) >> 5;  // 0..3071
    int lane = threadIdx.x & 31;
    int g    = wt >> 10;
    int rem  = wt & 1023;
    int mi   = rem >> 7;    // 0..7   (16-row vocab tile)
    int ni   = rem & 127;   // 0..127 (8-col hidden tile)

    const float* W    = (g == 0) ? Wr : ((g == 1) ? Wz : Wh);
    const float* bias = (g == 0) ? br : ((g == 1) ? bz : bh);

    int r0 = 16 * mi + (lane >> 2), r1 = r0 + 8;
    int pb = lane & 3;
    const float* pA0 = emb + r0 * E_ + 2 * pb;
    const float* pA1 = emb + r1 * E_ + 2 * pb;
    const float* pB  = W + (8 * ni + (lane >> 2)) * E_ + 2 * pb;

    float acc[4] = {0.f, 0.f, 0.f, 0.f};
#pragma unroll
    for (int kp = 0; kp < E_ / 2; kp += 8) {    // 16 iters of k16
        float2 va0 = *(const float2*)(pA0 + 2 * kp);
        float2 va2 = *(const float2*)(pA0 + 2 * kp + 8);
        float2 va1 = *(const float2*)(pA1 + 2 * kp);
        float2 va3 = *(const float2*)(pA1 + 2 * kp + 8);
        uint4 q0, q1;
        split2(va0.x, va0.y, q0.x, q0.y);
        split2(va2.x, va2.y, q0.z, q0.w);
        split2(va1.x, va1.y, q1.x, q1.y);
        split2(va3.x, va3.y, q1.z, q1.w);
        float2 vb0 = *(const float2*)(pB + 2 * kp);
        float2 vb1 = *(const float2*)(pB + 2 * kp + 8);
        uint4 b;
        split2(vb0.x, vb0.y, b.x, b.y);
        split2(vb1.x, vb1.y, b.z, b.w);
        mma3q(acc, q0, q1, b);
    }
#pragma unroll
    for (int i = 0; i < 4; i++) {
        int row = (i >= 2) ? r1 : r0;
        int col = 8 * ni + 2 * pb + (i & 1);
        g_eproj[g][row * H_ + col] = acc[i] + 2.0f * bias[col];
    }
}

// ---------------- persistent GRU recurrence ----------------
__global__ void __launch_bounds__(TPB, 1) k_gru(const int* __restrict__ x,
                                                const float* __restrict__ Ur,
                                                const float* __restrict__ Uz,
                                                const float* __restrict__ Uh) {
    extern __shared__ uint32_t smw[];
    const int GATEW = COLS * UST;     // 16448 words per gate
    int tid = threadIdx.x;
    int cta = blockIdx.x;
    int c0  = cta * COLS;

    // load + split + repack this CTA's U slices into SMEM (fragment-major)
    for (int g = 0; g < 3; g++) {
        const float* U = (g == 0) ? Ur : ((g == 1) ? Uz : Uh);
        uint32_t* dst = smw + g * GATEW;
        for (int i = tid; i < COLS * PAIRS; i += TPB) {
            int c = i >> 9, p = i & 511;
            float2 v = *(const float2*)(U + (size_t)(c0 + c) * H_ + 2 * p);
            uint32_t hi, lo;
            split2(v.x, v.y, hi, lo);
            int w = c * UST + (p >> 3) * 16 + (p & 3) * 4 + 2 * ((p >> 2) & 1);
            dst[w]     = hi;
            dst[w + 1] = lo;
        }
    }
    __syncthreads();

    int w = tid >> 5, lane = tid & 31;
    int mi = w >> 1, ni = w & 1;                 // 4 m-tiles x 2 n-tiles
    int r0 = 16 * mi + (lane >> 2), r1 = r0 + 8;
    int pb = lane & 3;

    int brow = (8 * ni + (lane >> 2)) * UST + pb * 4;
    const uint32_t* pBr = smw + brow;
    const uint32_t* pBz = smw + GATEW + brow;
    const uint32_t* pBh = smw + 2 * GATEW + brow;

    int aoff0 = r0 * 1024 + pb * 4;
    int aoff1 = r1 * 1024 + pb * 4;

    int colBase = c0 + 8 * ni + 2 * pb;          // even
    int pidx = colBase >> 1;                     // pair index 0..511
    int eoff = (pidx >> 3) * 16 + (pidx & 3) * 4 + 2 * ((pidx >> 2) & 1);
    int woff0 = r0 * 1024 + eoff;
    int woff1 = r1 * 1024 + eoff;

    float h_own[4] = {0.f, 0.f, 0.f, 0.f};       // this thread's 4 h values
    unsigned target = 0;

    for (int t = 0; t < S_; ++t) {
        const uint32_t* pA0 = g_hh + (size_t)t * SLOT + aoff0;
        const uint32_t* pA1 = g_hh + (size_t)t * SLOT + aoff1;

        // prefetch token + input-projection values early (consumed in epilogue)
        int tok0 = x[r0 * S_ + t];
        int tok1 = x[r1 * S_ + t];
        float xr[4], xz[4];
#pragma unroll
        for (int i = 0; i < 4; i++) {
            int tok = (i >= 2) ? tok1 : tok0;
            int col = colBase + (i & 1);
            xr[i] = g_eproj[0][tok * H_ + col];
            xz[i] = g_eproj[1][tok * H_ + col];
        }

        // ---- phase 1: r,z gates ----
        float accR[4] = {0.f, 0.f, 0.f, 0.f};
        float accZ[4] = {0.f, 0.f, 0.f, 0.f};
        uint4 a0 = *(const uint4*)pA0;
        uint4 a1 = *(const uint4*)pA1;
#pragma unroll 7
        for (int it = 0; it < 63; ++it) {
            uint4 n0 = *(const uint4*)(pA0 + (it + 1) * 16);
            uint4 n1 = *(const uint4*)(pA1 + (it + 1) * 16);
            uint4 brv = *(const uint4*)(pBr + it * 16);
            uint4 bzv = *(const uint4*)(pBz + it * 16);
            mma3q(accR, a0, a1, brv);
            mma3q(accZ, a0, a1, bzv);
            a0 = n0; a1 = n1;
        }
        {
            uint4 brv = *(const uint4*)(pBr + 63 * 16);
            uint4 bzv = *(const uint4*)(pBz + 63 * 16);
            mma3q(accR, a0, a1, brv);
            mma3q(accZ, a0, a1, bzv);
        }

        float zv[4], rh[4];
#pragma unroll
        for (int i = 0; i < 4; i++) {
            float rg = 1.f / (1.f + __expf(-(accR[i] + xr[i])));
            zv[i]    = 1.f / (1.f + __expf(-(accZ[i] + xz[i])));
            rh[i]    = rg * h_own[i];
        }
        {
            uint32_t hi, lo;
            split2(rh[0], rh[1], hi, lo);
            *(uint2*)(g_rh + woff0) = make_uint2(hi, lo);
            split2(rh[2], rh[3], hi, lo);
            *(uint2*)(g_rh + woff1) = make_uint2(hi, lo);
        }
        target += NCTA;
        gbar(target);

        // ---- phase 2: candidate h, state update ----
        float xh[4];
#pragma unroll
        for (int i = 0; i < 4; i++) {
            int tok = (i >= 2) ? tok1 : tok0;
            xh[i] = g_eproj[2][tok * H_ + colBase + (i & 1)];
        }
        float accH[4] = {0.f, 0.f, 0.f, 0.f};
        const uint32_t* qA0 = g_rh + aoff0;
        const uint32_t* qA1 = g_rh + aoff1;
        a0 = *(const uint4*)qA0;
        a1 = *(const uint4*)qA1;
#pragma unroll 7
        for (int it = 0; it < 63; ++it) {
            uint4 n0 = *(const uint4*)(qA0 + (it + 1) * 16);
            uint4 n1 = *(const uint4*)(qA1 + (it + 1) * 16);
            uint4 bhv = *(const uint4*)(pBh + it * 16);
            mma3q(accH, a0, a1, bhv);
            a0 = n0; a1 = n1;
        }
        {
            uint4 bhv = *(const uint4*)(pBh + 63 * 16);
            mma3q(accH, a0, a1, bhv);
        }

        uint32_t* nh = g_hh + (size_t)(t + 1) * SLOT;
#pragma unroll
        for (int i = 0; i < 4; i++) {
            float ht = tanhf(accH[i] + xh[i]);
            h_own[i] = (1.f - zv[i]) * ht + zv[i] * h_own[i];
        }
        {
            uint32_t hi, lo;
            split2(h_own[0], h_own[1], hi, lo);
            *(uint2*)(nh + woff0) = make_uint2(hi, lo);
            split2(h_own[2], h_own[3], hi, lo);
            *(uint2*)(nh + woff1) = make_uint2(hi, lo);
        }
        target += NCTA;
        gbar(target);
    }
}

// ---------------- logits: [32768,1024] @ [1024,128]^T + b_fc ----------------
__global__ void __launch_bounds__(256) k_logits(const float* __restrict__ bfc,
                                                float* __restrict__ out) {
    int w = threadIdx.x >> 5, lane = threadIdx.x & 31;
    int rowTile = blockIdx.x * 8 + w;                 // 0..2047
    int r0 = rowTile * 16 + (lane >> 2), r1 = r0 + 8; // same seq position block
    int pb = lane & 3;

    int s  = r0 >> 6;
    int b0 = r0 & 63, b1 = r1 & 63;
    const uint32_t* base = g_hh + (size_t)(s + 1) * SLOT;
    const uint32_t* pA0 = base + b0 * 1024 + pb * 4;
    const uint32_t* pA1 = base + b1 * 1024 + pb * 4;
    const uint32_t* pB  = g_wfc + (lane >> 2) * 1024 + pb * 4;

    float acc[16][4];
#pragma unroll
    for (int nt = 0; nt < 16; nt++)
#pragma unroll
        for (int i = 0; i < 4; i++) acc[nt][i] = 0.f;

    for (int it = 0; it < 64; ++it) {
        uint4 q0 = *(const uint4*)(pA0 + it * 16);
        uint4 q1 = *(const uint4*)(pA1 + it * 16);
#pragma unroll
        for (int nt = 0; nt < 16; nt++) {
            uint4 b = *(const uint4*)(pB + nt * 8 * 1024 + it * 16);
            mma3q(acc[nt], q0, q1, b);
        }
    }
#pragma unroll
    for (int nt = 0; nt < 16; nt++)
#pragma unroll
        for (int i = 0; i < 4; i++) {
            int row = (i >= 2) ? r1 : r0;
            int v   = nt * 8 + 2 * pb + (i & 1);
            int ss  = row >> 6;
            int bb  = row & 63;
            out[bb * (S_ * V_) + ss * V_ + v] = acc[nt][i] + bfc[v];
        }
}

// ---------------- h_last: reconstruct fp32 from slot 512 ----------------
__global__ void k_hlast(float* __restrict__ out) {
    int i = blockIdx.x * blockDim.x + threadIdx.x;    // 32768 pairs
    int b = i >> 9, p = i & 511;
    int wrd = S_ * SLOT + b * 1024 + (p >> 3) * 16 + (p & 3) * 4 + 2 * ((p >> 2) & 1);
    uint2 v = *(const uint2*)(g_hh + wrd);
    __nv_bfloat162 vh = *reinterpret_cast<__nv_bfloat162*>(&v.x);
    __nv_bfloat162 vl = *reinterpret_cast<__nv_bfloat162*>(&v.y);
    float* o = out + (size_t)B_ * S_ * V_ + b * H_ + 2 * p;
    o[0] = __bfloat162float(vh.x) + __bfloat162float(vl.x);
    o[1] = __bfloat162float(vh.y) + __bfloat162float(vl.y);
}

// ---------------- launch ----------------
extern "C" void kernel_launch(void* const* d_in, const int* in_sizes, int n_in,
                              void* d_out, int out_size) {
    const int*   x   = (const int*)d_in[0];
    const float* emb = (const float*)d_in[1];
    const float* Wr  = (const float*)d_in[2];
    const float* Ur  = (const float*)d_in[3];
    const float* br  = (const float*)d_in[4];
    const float* Wz  = (const float*)d_in[5];
    const float* Uz  = (const float*)d_in[6];
    const float* bz  = (const float*)d_in[7];
    const float* Wh  = (const float*)d_in[8];
    const float* Uh  = (const float*)d_in[9];
    const float* bh  = (const float*)d_in[10];
    const float* Wfc = (const float*)d_in[11];
    const float* bfc = (const float*)d_in[12];
    float* out = (float*)d_out;

    const int smem_bytes = 3 * COLS * UST * 4;  // 197376 B
    cudaFuncSetAttribute(k_gru, cudaFuncAttributeMaxDynamicSharedMemorySize,
                         smem_bytes);

    k_init<<<64, 256>>>();
    k_wfcsplit<<<256, 256>>>(Wfc);
    k_embproj<<<384, 256>>>(emb, Wr, Wz, Wh, br, bz, bh);
    k_gru<<<NCTA, TPB, smem_bytes>>>(x, Ur, Uz, Uh);
    k_logits<<<256, 256>>>(bfc, out);
    if (out_size >= B_ * S_ * V_ + B_ * H_) {
        k_hlast<<<128, 256>>>(out);
    }
}